// round 16
// baseline (speedup 1.0000x reference)
#include <cuda.h>
#include <cuda_runtime.h>
#include <cuda_fp16.h>
#include <math.h>

#define D_MODEL 2048
#define INNER   4096
#define NHEADS  64
#define HEADDIM 64
#define D_CONV  4
#define BATCH   2
#define SEQLEN  4096
#define BL (BATCH * SEQLEN)      // 8192

// ---------------- scratch (device globals; no allocation allowed) ----------
__device__ float  g_dt[(size_t)BL * NHEADS];            // softplus(dt)
__device__ __half g_hx[(size_t)BL * D_MODEL];           // hidden fp16
__device__ __half g_iw[(size_t)INNER * D_MODEL];        // in_w fp16
__device__ __half g_gw[(size_t)INNER * D_MODEL];        // gate_w fp16
__device__ __half g_ow[(size_t)D_MODEL * INNER];        // out_w fp16
__device__ __half g_projh[(size_t)BL * INNER];          // in_proj out fp16
__device__ __half g_gateh[(size_t)BL * INNER];          // sigmoid(gate) fp16
__device__ __half g_xh[(size_t)BL * INNER];             // conv+silu X fp16
__device__ __half g_cb[(size_t)BL * INNER];             // comb fp16

// ===================== PTX helpers ==========================================
__device__ __forceinline__ uint32_t smem_to_u32(const void* smem_ptr) {
    uint32_t addr;
    asm("{ .reg .u64 tmp; cvta.to.shared.u64 tmp, %1; cvt.u32.u64 %0, tmp; }"
        : "=r"(addr) : "l"(smem_ptr));
    return addr;
}

#define MBARRIER_INIT(mbar, count) \
    asm volatile("mbarrier.init.shared.b64 [%0], %1;" \
        :: "r"((uint32_t)(mbar)), "r"((uint32_t)(count)) : "memory")

#define MBARRIER_EXPECT_TX(mbar, bytes) \
    asm volatile("mbarrier.arrive.expect_tx.shared.b64 _, [%0], %1;" \
        :: "r"((uint32_t)(mbar)), "r"((uint32_t)(bytes)) : "memory")

#define MBARRIER_WAIT_PARITY(mbar, parity) do { \
    uint32_t _m = (uint32_t)(mbar); uint32_t _p = (uint32_t)(parity); uint32_t _d; \
    asm volatile( \
        "{\n\t.reg .pred p;\n\t" \
        "mbarrier.try_wait.parity.acquire.cta.shared::cta.b64 p, [%1], %2;\n\t" \
        "selp.b32 %0, 1, 0, p;\n\t}" \
        : "=r"(_d) : "r"(_m), "r"(_p) : "memory"); \
    if (!_d) { \
        asm volatile( \
            "{\n\t.reg .pred P1;\n\t" \
            "WAIT_LOOP_%=:\n\t" \
            "mbarrier.try_wait.parity.acquire.cta.shared::cta.b64 P1, [%0], %1, 0x989680;\n\t" \
            "@P1 bra.uni WAIT_DONE_%=;\n\t" \
            "bra.uni WAIT_LOOP_%=;\n\t" \
            "WAIT_DONE_%=:\n\t}" \
            :: "r"(_m), "r"(_p) : "memory"); \
    } \
} while (0)

#define TMA2D(smemaddr, tmapptr, cx, cy, mbar) \
    asm volatile( \
        "cp.async.bulk.tensor.2d.shared::cta.global.tile.mbarrier::complete_tx::bytes " \
        "[%0], [%1, {%2, %3}], [%4];" \
        :: "r"((uint32_t)(smemaddr)), "l"(tmapptr), "r"((int)(cx)), "r"((int)(cy)), \
           "r"((uint32_t)(mbar)) : "memory")

__device__ __forceinline__ void ldsm_x4(uint32_t* r, uint32_t addr) {
    asm volatile("ldmatrix.sync.aligned.m8n8.x4.shared.b16 {%0,%1,%2,%3}, [%4];"
        : "=r"(r[0]), "=r"(r[1]), "=r"(r[2]), "=r"(r[3]) : "r"(addr));
}

__device__ __forceinline__ void mma16816(float* d, const uint32_t* a, const uint32_t* b) {
    asm volatile(
        "mma.sync.aligned.m16n8k16.row.col.f32.f16.f16.f32 "
        "{%0,%1,%2,%3}, {%4,%5,%6,%7}, {%8,%9}, {%0,%1,%2,%3};"
        : "+f"(d[0]), "+f"(d[1]), "+f"(d[2]), "+f"(d[3])
        : "r"(a[0]), "r"(a[1]), "r"(a[2]), "r"(a[3]), "r"(b[0]), "r"(b[1]));
}

#define SWZ(o) ((o) ^ (((o) >> 3) & 0x70))

// ===================== HMMA GEMM (R13 config: 2 CTAs/SM) =====================
#define TILE_M 128
#define TILE_N 128
#define KC 64
#define NST 3
#define SOFF_B 16384
#define STAGE 32768
#define GEMM_SMEM (1024 + NST * STAGE)

template<int EPI>
__global__ __launch_bounds__(256, 2)
void hmma_gemm(const __grid_constant__ CUtensorMap tA,
               const __grid_constant__ CUtensorMap tB,
               void* __restrict__ Cout, int Ntotal, int K)
{
    extern __shared__ __align__(1024) char smem[];
    const uint32_t sb = smem_to_u32(smem);
    const uint32_t sdata = sb + 1024;
    const int tid = threadIdx.x;
    const int wid = tid >> 5;
    const int lane = tid & 31;
    const int wm = wid >> 2;
    const int wn = wid & 3;
    const int bm = blockIdx.y * TILE_M;
    const int bn = blockIdx.x * TILE_N;

    uint32_t full[NST];
#pragma unroll
    for (int s = 0; s < NST; s++) full[s] = sb + 64 + s * 16;

    if (tid == 0) {
#pragma unroll
        for (int s = 0; s < NST; s++) MBARRIER_INIT(full[s], 1);
    }
    __syncthreads();

    const int NC = K / KC;

    if (tid == 0) {
#pragma unroll
        for (int s = 0; s < NST; s++) {
            if (s < NC) {
                uint32_t st = sdata + s * STAGE;
                MBARRIER_EXPECT_TX(full[s], STAGE);
                TMA2D(st, &tA, s * KC, bm, full[s]);
                TMA2D(st + SOFF_B, &tB, s * KC, bn, full[s]);
            }
        }
    }

    uint32_t abase[4], bbase[2];
#pragma unroll
    for (int mt = 0; mt < 4; mt++) {
        int row = wm * 64 + mt * 16 + (lane & 15);
        abase[mt] = (uint32_t)(row * 128 + ((lane >> 4) * 16));
    }
#pragma unroll
    for (int q = 0; q < 2; q++) {
        int row = wn * 32 + q * 16 + ((lane >> 4) << 3) + (lane & 7);
        bbase[q] = (uint32_t)(row * 128 + (((lane >> 3) & 1) * 16));
    }

    float acc[4][4][4];
#pragma unroll
    for (int mt = 0; mt < 4; mt++)
#pragma unroll
        for (int nt = 0; nt < 4; nt++)
#pragma unroll
            for (int k = 0; k < 4; k++) acc[mt][nt][k] = 0.f;

    int ph[NST];
#pragma unroll
    for (int s = 0; s < NST; s++) ph[s] = 0;

    for (int c = 0; c < NC; c++) {
        const int s = c % NST;
        const uint32_t st = sdata + s * STAGE;
        MBARRIER_WAIT_PARITY(full[s], ph[s]);
        ph[s] ^= 1;

#pragma unroll
        for (int ks = 0; ks < 4; ks++) {
            const uint32_t kb = ks * 32;
            uint32_t af[4][4], bf[2][4];
#pragma unroll
            for (int mt = 0; mt < 4; mt++) {
                uint32_t off = SWZ(abase[mt] + kb);
                ldsm_x4(af[mt], st + off);
            }
#pragma unroll
            for (int q = 0; q < 2; q++) {
                uint32_t off = SWZ(bbase[q] + kb);
                ldsm_x4(bf[q], st + SOFF_B + off);
            }
#pragma unroll
            for (int mt = 0; mt < 4; mt++) {
#pragma unroll
                for (int nt = 0; nt < 4; nt++) {
                    const uint32_t* Bf = &bf[nt >> 1][(nt & 1) * 2];
                    mma16816(acc[mt][nt], af[mt], Bf);
                }
            }
        }
        __syncthreads();
        if (tid == 0 && c + NST < NC) {
            MBARRIER_EXPECT_TX(full[s], STAGE);
            TMA2D(st, &tA, (c + NST) * KC, bm, full[s]);
            TMA2D(st + SOFF_B, &tB, (c + NST) * KC, bn, full[s]);
        }
    }

    const int g = lane >> 2;
    const int nq = (lane & 3) * 2;
#pragma unroll
    for (int mt = 0; mt < 4; mt++) {
        int r0 = bm + wm * 64 + mt * 16 + g;
#pragma unroll
        for (int nt = 0; nt < 4; nt++) {
            int cc = bn + wn * 32 + nt * 8 + nq;
            float2 v0 = make_float2(acc[mt][nt][0], acc[mt][nt][1]);
            float2 v1 = make_float2(acc[mt][nt][2], acc[mt][nt][3]);
            if (EPI == 1) {
                v0.x = 1.f / (1.f + expf(-v0.x));
                v0.y = 1.f / (1.f + expf(-v0.y));
                v1.x = 1.f / (1.f + expf(-v1.x));
                v1.y = 1.f / (1.f + expf(-v1.y));
            }
            if (EPI == 0) {
                float* C = (float*)Cout;
                *reinterpret_cast<float2*>(C + (size_t)r0 * Ntotal + cc) = v0;
                *reinterpret_cast<float2*>(C + (size_t)(r0 + 8) * Ntotal + cc) = v1;
            } else {
                __half* C = (__half*)Cout;
                *reinterpret_cast<__half2*>(C + (size_t)r0 * Ntotal + cc) =
                    __floats2half2_rn(v0.x, v0.y);
                *reinterpret_cast<__half2*>(C + (size_t)(r0 + 8) * Ntotal + cc) =
                    __floats2half2_rn(v1.x, v1.y);
            }
        }
    }
}

// ===================== merged fp32 -> fp16 convert (4 tensors, 1 launch) =====
#define CVT_Q0 (BL * D_MODEL / 4)
#define CVT_Q1 (INNER * D_MODEL / 4)
__global__ __launch_bounds__(256)
void cvt_f16_all(const float* __restrict__ s0, __half* __restrict__ d0,
                 const float* __restrict__ s1, __half* __restrict__ d1,
                 const float* __restrict__ s2, __half* __restrict__ d2,
                 const float* __restrict__ s3, __half* __restrict__ d3)
{
    long long q = (long long)blockIdx.x * 256 + threadIdx.x;
    const float* src; __half* dst;
    if (q < CVT_Q0)                  { src = s0; dst = d0; }
    else if ((q -= CVT_Q0) < CVT_Q1) { src = s1; dst = d1; }
    else if ((q -= CVT_Q1) < CVT_Q1) { src = s2; dst = d2; }
    else if ((q -= CVT_Q1) < CVT_Q1) { src = s3; dst = d3; }
    else return;
    long long i = q * 4;
    float4 v = *reinterpret_cast<const float4*>(src + i);
    *reinterpret_cast<__half2*>(dst + i)     = __halves2half2(__float2half_rn(v.x), __float2half_rn(v.y));
    *reinterpret_cast<__half2*>(dst + i + 2) = __halves2half2(__float2half_rn(v.z), __float2half_rn(v.w));
}

// ---------------- conv(K=4, causal, depthwise) + SiLU + dt(softplus) -------
// Block per (b,l); 512 threads; thread owns 8 contiguous channels.
// 16B loads per row, X in registers, smem only for the tiny dt reduce.
__global__ __launch_bounds__(512)
void conv_dt_kernel(const __half* __restrict__ proj,
                    const float* __restrict__ cw,
                    const float* __restrict__ cbias,
                    const float* __restrict__ dtw,
                    const float* __restrict__ dtb,
                    __half* __restrict__ Xout,
                    float* __restrict__ dt_out)
{
    const int bl = blockIdx.x;
    const int l = bl % SEQLEN;
    const int tid = threadIdx.x;         // 0..511
    const int c0 = tid * 8;              // 8 channels per thread
    const size_t rowbase = (size_t)bl * INNER + c0;

    __shared__ float spart[NHEADS][8];

    // conv weights for my 8 channels (float4 per channel = 4 taps)
    float4 cwv[8];
#pragma unroll
    for (int j = 0; j < 8; j++)
        cwv[j] = reinterpret_cast<const float4*>(cw)[c0 + j];

    float acc[8];
    {
        float4 b0 = *reinterpret_cast<const float4*>(cbias + c0);
        float4 b1 = *reinterpret_cast<const float4*>(cbias + c0 + 4);
        acc[0] = b0.x; acc[1] = b0.y; acc[2] = b0.z; acc[3] = b0.w;
        acc[4] = b1.x; acc[5] = b1.y; acc[6] = b1.z; acc[7] = b1.w;
    }

#pragma unroll
    for (int k = 0; k < D_CONV; k++) {
        int ll = l + k - (D_CONV - 1);
        if (ll >= 0) {
            uint4 raw = *reinterpret_cast<const uint4*>(
                proj + rowbase + (ptrdiff_t)(k - (D_CONV - 1)) * INNER);
            const __half2* h2 = reinterpret_cast<const __half2*>(&raw);
#pragma unroll
            for (int j = 0; j < 4; j++) {
                float2 fv = __half22float2(h2[j]);
                const float* w0 = reinterpret_cast<const float*>(&cwv[2 * j]);
                const float* w1 = reinterpret_cast<const float*>(&cwv[2 * j + 1]);
                acc[2 * j]     = fmaf(w0[k], fv.x, acc[2 * j]);
                acc[2 * j + 1] = fmaf(w1[k], fv.y, acc[2 * j + 1]);
            }
        }
    }

    // SiLU, dt partial, X store (one 16B store)
    float dtp = 0.f;
    {
        float4 dw0 = *reinterpret_cast<const float4*>(dtw + c0);
        float4 dw1 = *reinterpret_cast<const float4*>(dtw + c0 + 4);
        const float* dws = reinterpret_cast<const float*>(&dw0);
        uint4 outv;
        __half2* oh = reinterpret_cast<__half2*>(&outv);
#pragma unroll
        for (int j = 0; j < 8; j++) {
            float s = acc[j] / (1.f + expf(-acc[j]));
            acc[j] = s;
            float w = (j < 4) ? dws[j] : reinterpret_cast<const float*>(&dw1)[j - 4];
            dtp = fmaf(s, w, dtp);
        }
#pragma unroll
        for (int j = 0; j < 4; j++)
            oh[j] = __floats2half2_rn(acc[2 * j], acc[2 * j + 1]);
        *reinterpret_cast<uint4*>(Xout + rowbase) = outv;
    }

    spart[tid >> 3][tid & 7] = dtp;
    __syncthreads();

    if (tid < NHEADS) {
        float v = dtb[tid];
#pragma unroll
        for (int q = 0; q < 8; q++) v += spart[tid][q];
        float sp = (v > 20.f) ? v : log1pf(expf(v));
        dt_out[(size_t)bl * NHEADS + tid] = sp;
    }
}

// ---------------- SSM scan + output fusion (half2-vectorized) ---------------
// block per (b,h); threads (p2=32, s=32); thread owns channel pair 2*p2, 2*p2+1.
#define NSEG 32
#define SEG (SEQLEN / NSEG)     // 128

__global__ __launch_bounds__(1024, 1)
void scan_kernel(const __half* __restrict__ X,
                 const float* __restrict__ dt,
                 const __half* __restrict__ gate,
                 const float* __restrict__ A_log,
                 const float* __restrict__ Bv,
                 const float* __restrict__ Cv,
                 const float* __restrict__ Dv,
                 __half* __restrict__ comb)
{
    const int bh = blockIdx.x;
    const int h = bh % NHEADS;
    const int b = bh / NHEADS;
    const int p2 = threadIdx.x;     // 0..31 (channel pair)
    const int s = threadIdx.y;      // 0..31 (segment)

    const int ch0 = 2 * p2;
    const int hp0 = h * HEADDIM + ch0;
    const float ac0 = -expf(A_log[hp0]);
    const float ac1 = -expf(A_log[hp0 + 1]);
    const float2 Bc = *reinterpret_cast<const float2*>(Bv + hp0);
    const float2 Cc = *reinterpret_cast<const float2*>(Cv + hp0);
    const float2 Dc = *reinterpret_cast<const float2*>(Dv + hp0);

    const size_t baseE = ((size_t)b * SEQLEN * INNER + (size_t)h * HEADDIM + ch0);
    const size_t baseDt = (size_t)b * SEQLEN * NHEADS + h;
    const int l0 = s * SEG;

    __shared__ float2 agg_a[NSEG][32];
    __shared__ float2 agg_u[NSEG][32];
    __shared__ float2 pre[NSEG][32];

    // pass 1: segment summaries
    float ap0 = 1.f, ss0 = 0.f, ap1 = 1.f, ss1 = 0.f;
    for (int i = 0; i < SEG; i++) {
        int l = l0 + i;
        float d = dt[baseDt + (size_t)l * NHEADS];
        float2 xv = __half22float2(
            *reinterpret_cast<const __half2*>(X + baseE + (size_t)l * INNER));
        float a0 = expf(d * ac0), a1 = expf(d * ac1);
        ap0 *= a0; ap1 *= a1;
        ss0 = fmaf(a0, ss0, d * Bc.x * xv.x);
        ss1 = fmaf(a1, ss1, d * Bc.y * xv.y);
    }
    agg_a[s][p2] = make_float2(ap0, ap1);
    agg_u[s][p2] = make_float2(ss0, ss1);
    __syncthreads();

    // prefix over segments (warp s==0; 32 threads, each its channel pair)
    if (s == 0) {
        float st0 = 0.f, st1 = 0.f;
#pragma unroll
        for (int j = 0; j < NSEG; j++) {
            pre[j][p2] = make_float2(st0, st1);
            float2 aa = agg_a[j][p2];
            float2 uu = agg_u[j][p2];
            st0 = fmaf(aa.x, st0, uu.x);
            st1 = fmaf(aa.y, st1, uu.y);
        }
    }
    __syncthreads();

    // pass 2: replay with carry, fuse y*gate, half2 out
    float2 sp = pre[s][p2];
    for (int i = 0; i < SEG; i++) {
        int l = l0 + i;
        size_t idx = baseE + (size_t)l * INNER;
        float d = dt[baseDt + (size_t)l * NHEADS];
        float2 xv = __half22float2(*reinterpret_cast<const __half2*>(X + idx));
        float a0 = expf(d * ac0), a1 = expf(d * ac1);
        sp.x = fmaf(a0, sp.x, d * Bc.x * xv.x);
        sp.y = fmaf(a1, sp.y, d * Bc.y * xv.y);
        float2 gv = __half22float2(*reinterpret_cast<const __half2*>(gate + idx));
        float y0 = fmaf(Cc.x, sp.x, Dc.x * xv.x) * gv.x;
        float y1 = fmaf(Cc.y, sp.y, Dc.y * xv.y) * gv.y;
        *reinterpret_cast<__half2*>(comb + idx) = __floats2half2_rn(y0, y1);
    }
}

// ===================== host side ============================================
typedef CUresult (*TmEncodeFn)(CUtensorMap*, CUtensorMapDataType, cuuint32_t,
                               void*, const cuuint64_t*, const cuuint64_t*,
                               const cuuint32_t*, const cuuint32_t*,
                               CUtensorMapInterleave, CUtensorMapSwizzle,
                               CUtensorMapL2promotion, CUtensorMapFloatOOBfill);

static void make_tm(TmEncodeFn fn, CUtensorMap* tm, const void* ptr,
                    int rows, int K, int boxRows)
{
    cuuint64_t dims[2]    = {(cuuint64_t)K, (cuuint64_t)rows};
    cuuint64_t strides[1] = {(cuuint64_t)K * 2};
    cuuint32_t box[2]     = {64u, (cuuint32_t)boxRows};
    cuuint32_t es[2]      = {1u, 1u};
    fn(tm, CU_TENSOR_MAP_DATA_TYPE_FLOAT16, 2, (void*)ptr,
       dims, strides, box, es,
       CU_TENSOR_MAP_INTERLEAVE_NONE, CU_TENSOR_MAP_SWIZZLE_128B,
       CU_TENSOR_MAP_L2_PROMOTION_L2_128B, CU_TENSOR_MAP_FLOAT_OOB_FILL_NONE);
}

extern "C" void kernel_launch(void* const* d_in, const int* in_sizes, int n_in,
                              void* d_out, int out_size)
{
    const float* hidden = (const float*)d_in[0];
    const float* in_w   = (const float*)d_in[1];
    const float* gate_w = (const float*)d_in[2];
    const float* out_w  = (const float*)d_in[3];
    const float* conv_w = (const float*)d_in[4];
    const float* conv_b = (const float*)d_in[5];
    const float* dt_w   = (const float*)d_in[6];
    const float* dt_b   = (const float*)d_in[7];
    const float* A_log  = (const float*)d_in[8];
    const float* Bv     = (const float*)d_in[9];
    const float* Cv     = (const float*)d_in[10];
    const float* Dv     = (const float*)d_in[11];
    float* out          = (float*)d_out;

    float* dtbuf;
    __half *hx, *iw, *gw, *ow, *projh, *gateh, *xh, *cbuf;
    cudaGetSymbolAddress((void**)&dtbuf, g_dt);
    cudaGetSymbolAddress((void**)&hx, g_hx);
    cudaGetSymbolAddress((void**)&iw, g_iw);
    cudaGetSymbolAddress((void**)&gw, g_gw);
    cudaGetSymbolAddress((void**)&ow, g_ow);
    cudaGetSymbolAddress((void**)&projh, g_projh);
    cudaGetSymbolAddress((void**)&gateh, g_gateh);
    cudaGetSymbolAddress((void**)&xh, g_xh);
    cudaGetSymbolAddress((void**)&cbuf, g_cb);

    TmEncodeFn enc = nullptr;
    {
        void* p = nullptr;
        cudaDriverEntryPointQueryResult qr;
        cudaGetDriverEntryPointByVersion("cuTensorMapEncodeTiled", &p, 12000,
                                         cudaEnableDefault, &qr);
        enc = (TmEncodeFn)p;
    }

    CUtensorMap tm_hx, tm_iw, tm_gw, tm_ow, tm_cb;
    make_tm(enc, &tm_hx, hx, BL,      D_MODEL, 128);
    make_tm(enc, &tm_iw, iw, INNER,   D_MODEL, 128);
    make_tm(enc, &tm_gw, gw, INNER,   D_MODEL, 128);
    make_tm(enc, &tm_ow, ow, D_MODEL, INNER,   128);
    make_tm(enc, &tm_cb, cbuf, BL,    INNER,   128);

    cudaFuncSetAttribute((const void*)hmma_gemm<0>,
                         cudaFuncAttributeMaxDynamicSharedMemorySize, GEMM_SMEM);
    cudaFuncSetAttribute((const void*)hmma_gemm<1>,
                         cudaFuncAttributeMaxDynamicSharedMemorySize, GEMM_SMEM);
    cudaFuncSetAttribute((const void*)hmma_gemm<2>,
                         cudaFuncAttributeMaxDynamicSharedMemorySize, GEMM_SMEM);

    // 0) all fp32->fp16 converts in one launch
    {
        long long totq = (long long)CVT_Q0 + 3LL * CVT_Q1;
        int blocks = (int)((totq + 255) / 256);
        cvt_f16_all<<<blocks, 256>>>(hidden, hx, in_w, iw, gate_w, gw, out_w, ow);
    }

    // 1) in_proj -> fp16
    {
        dim3 grid(INNER / TILE_N, BL / TILE_M);
        hmma_gemm<2><<<grid, 256, GEMM_SMEM>>>(tm_hx, tm_iw, projh, INNER, D_MODEL);
    }
    // 2) gate -> sigmoid -> fp16
    {
        dim3 grid(INNER / TILE_N, BL / TILE_M);
        hmma_gemm<1><<<grid, 256, GEMM_SMEM>>>(tm_hx, tm_gw, gateh, INNER, D_MODEL);
    }
    // 3) conv + silu + dt (vectorized, register-resident)
    conv_dt_kernel<<<BL, 512>>>(projh, conv_w, conv_b, dt_w, dt_b, xh, dtbuf);
    // 4) SSM scan (half2-vectorized) fused with y, gate
    {
        dim3 blk(32, NSEG);
        scan_kernel<<<BATCH * NHEADS, blk>>>(xh, dtbuf, gateh, A_log, Bv, Cv, Dv, cbuf);
    }
    // 5) out_proj -> fp32 final
    {
        dim3 grid(D_MODEL / TILE_N, BL / TILE_M);
        hmma_gemm<0><<<grid, 256, GEMM_SMEM>>>(tm_cb, tm_ow, out, D_MODEL, INNER);
    }
}

// round 17
// speedup vs baseline: 1.1444x; 1.1444x over previous
#include <cuda.h>
#include <cuda_runtime.h>
#include <cuda_fp16.h>
#include <math.h>

#define D_MODEL 2048
#define INNER   4096
#define NHEADS  64
#define HEADDIM 64
#define D_CONV  4
#define BATCH   2
#define SEQLEN  4096
#define BL (BATCH * SEQLEN)      // 8192

// ---------------- scratch (device globals; no allocation allowed) ----------
__device__ float  g_dt[(size_t)BL * NHEADS];            // softplus(dt)
__device__ __half g_hx[(size_t)BL * D_MODEL];           // hidden fp16
__device__ __half g_iw[(size_t)INNER * D_MODEL];        // in_w fp16
__device__ __half g_gw[(size_t)INNER * D_MODEL];        // gate_w fp16
__device__ __half g_ow[(size_t)D_MODEL * INNER];        // out_w fp16
__device__ __half g_projh[(size_t)BL * INNER];          // in_proj out fp16
__device__ __half g_gateh[(size_t)BL * INNER];          // sigmoid(gate) fp16
__device__ __half g_xh[(size_t)BL * INNER];             // conv+silu X fp16
__device__ __half g_cb[(size_t)BL * INNER];             // comb fp16

// ===================== PTX helpers ==========================================
__device__ __forceinline__ uint32_t smem_to_u32(const void* smem_ptr) {
    uint32_t addr;
    asm("{ .reg .u64 tmp; cvta.to.shared.u64 tmp, %1; cvt.u32.u64 %0, tmp; }"
        : "=r"(addr) : "l"(smem_ptr));
    return addr;
}

#define MBARRIER_INIT(mbar, count) \
    asm volatile("mbarrier.init.shared.b64 [%0], %1;" \
        :: "r"((uint32_t)(mbar)), "r"((uint32_t)(count)) : "memory")

#define MBARRIER_EXPECT_TX(mbar, bytes) \
    asm volatile("mbarrier.arrive.expect_tx.shared.b64 _, [%0], %1;" \
        :: "r"((uint32_t)(mbar)), "r"((uint32_t)(bytes)) : "memory")

#define MBARRIER_WAIT_PARITY(mbar, parity) do { \
    uint32_t _m = (uint32_t)(mbar); uint32_t _p = (uint32_t)(parity); uint32_t _d; \
    asm volatile( \
        "{\n\t.reg .pred p;\n\t" \
        "mbarrier.try_wait.parity.acquire.cta.shared::cta.b64 p, [%1], %2;\n\t" \
        "selp.b32 %0, 1, 0, p;\n\t}" \
        : "=r"(_d) : "r"(_m), "r"(_p) : "memory"); \
    if (!_d) { \
        asm volatile( \
            "{\n\t.reg .pred P1;\n\t" \
            "WAIT_LOOP_%=:\n\t" \
            "mbarrier.try_wait.parity.acquire.cta.shared::cta.b64 P1, [%0], %1, 0x989680;\n\t" \
            "@P1 bra.uni WAIT_DONE_%=;\n\t" \
            "bra.uni WAIT_LOOP_%=;\n\t" \
            "WAIT_DONE_%=:\n\t}" \
            :: "r"(_m), "r"(_p) : "memory"); \
    } \
} while (0)

#define TMA2D(smemaddr, tmapptr, cx, cy, mbar) \
    asm volatile( \
        "cp.async.bulk.tensor.2d.shared::cta.global.tile.mbarrier::complete_tx::bytes " \
        "[%0], [%1, {%2, %3}], [%4];" \
        :: "r"((uint32_t)(smemaddr)), "l"(tmapptr), "r"((int)(cx)), "r"((int)(cy)), \
           "r"((uint32_t)(mbar)) : "memory")

__device__ __forceinline__ void ldsm_x4(uint32_t* r, uint32_t addr) {
    asm volatile("ldmatrix.sync.aligned.m8n8.x4.shared.b16 {%0,%1,%2,%3}, [%4];"
        : "=r"(r[0]), "=r"(r[1]), "=r"(r[2]), "=r"(r[3]) : "r"(addr));
}

__device__ __forceinline__ void mma16816(float* d, const uint32_t* a, const uint32_t* b) {
    asm volatile(
        "mma.sync.aligned.m16n8k16.row.col.f32.f16.f16.f32 "
        "{%0,%1,%2,%3}, {%4,%5,%6,%7}, {%8,%9}, {%0,%1,%2,%3};"
        : "+f"(d[0]), "+f"(d[1]), "+f"(d[2]), "+f"(d[3])
        : "r"(a[0]), "r"(a[1]), "r"(a[2]), "r"(a[3]), "r"(b[0]), "r"(b[1]));
}

#define SWZ(o) ((o) ^ (((o) >> 3) & 0x70))

// ===================== HMMA GEMM (R13 config: 2 CTAs/SM) =====================
#define TILE_M 128
#define TILE_N 128
#define KC 64
#define NST 3
#define SOFF_B 16384
#define STAGE 32768
#define GEMM_SMEM (1024 + NST * STAGE)

template<int EPI>
__global__ __launch_bounds__(256, 2)
void hmma_gemm(const __grid_constant__ CUtensorMap tA,
               const __grid_constant__ CUtensorMap tB,
               void* __restrict__ Cout, int Ntotal, int K)
{
    extern __shared__ __align__(1024) char smem[];
    const uint32_t sb = smem_to_u32(smem);
    const uint32_t sdata = sb + 1024;
    const int tid = threadIdx.x;
    const int wid = tid >> 5;
    const int lane = tid & 31;
    const int wm = wid >> 2;
    const int wn = wid & 3;
    const int bm = blockIdx.y * TILE_M;
    const int bn = blockIdx.x * TILE_N;

    uint32_t full[NST];
#pragma unroll
    for (int s = 0; s < NST; s++) full[s] = sb + 64 + s * 16;

    if (tid == 0) {
#pragma unroll
        for (int s = 0; s < NST; s++) MBARRIER_INIT(full[s], 1);
    }
    __syncthreads();

    const int NC = K / KC;

    if (tid == 0) {
#pragma unroll
        for (int s = 0; s < NST; s++) {
            if (s < NC) {
                uint32_t st = sdata + s * STAGE;
                MBARRIER_EXPECT_TX(full[s], STAGE);
                TMA2D(st, &tA, s * KC, bm, full[s]);
                TMA2D(st + SOFF_B, &tB, s * KC, bn, full[s]);
            }
        }
    }

    uint32_t abase[4], bbase[2];
#pragma unroll
    for (int mt = 0; mt < 4; mt++) {
        int row = wm * 64 + mt * 16 + (lane & 15);
        abase[mt] = (uint32_t)(row * 128 + ((lane >> 4) * 16));
    }
#pragma unroll
    for (int q = 0; q < 2; q++) {
        int row = wn * 32 + q * 16 + ((lane >> 4) << 3) + (lane & 7);
        bbase[q] = (uint32_t)(row * 128 + (((lane >> 3) & 1) * 16));
    }

    float acc[4][4][4];
#pragma unroll
    for (int mt = 0; mt < 4; mt++)
#pragma unroll
        for (int nt = 0; nt < 4; nt++)
#pragma unroll
            for (int k = 0; k < 4; k++) acc[mt][nt][k] = 0.f;

    int ph[NST];
#pragma unroll
    for (int s = 0; s < NST; s++) ph[s] = 0;

    for (int c = 0; c < NC; c++) {
        const int s = c % NST;
        const uint32_t st = sdata + s * STAGE;
        MBARRIER_WAIT_PARITY(full[s], ph[s]);
        ph[s] ^= 1;

#pragma unroll
        for (int ks = 0; ks < 4; ks++) {
            const uint32_t kb = ks * 32;
            uint32_t af[4][4], bf[2][4];
#pragma unroll
            for (int mt = 0; mt < 4; mt++) {
                uint32_t off = SWZ(abase[mt] + kb);
                ldsm_x4(af[mt], st + off);
            }
#pragma unroll
            for (int q = 0; q < 2; q++) {
                uint32_t off = SWZ(bbase[q] + kb);
                ldsm_x4(bf[q], st + SOFF_B + off);
            }
#pragma unroll
            for (int mt = 0; mt < 4; mt++) {
#pragma unroll
                for (int nt = 0; nt < 4; nt++) {
                    const uint32_t* Bf = &bf[nt >> 1][(nt & 1) * 2];
                    mma16816(acc[mt][nt], af[mt], Bf);
                }
            }
        }
        __syncthreads();
        if (tid == 0 && c + NST < NC) {
            MBARRIER_EXPECT_TX(full[s], STAGE);
            TMA2D(st, &tA, (c + NST) * KC, bm, full[s]);
            TMA2D(st + SOFF_B, &tB, (c + NST) * KC, bn, full[s]);
        }
    }

    const int g = lane >> 2;
    const int nq = (lane & 3) * 2;
#pragma unroll
    for (int mt = 0; mt < 4; mt++) {
        int r0 = bm + wm * 64 + mt * 16 + g;
#pragma unroll
        for (int nt = 0; nt < 4; nt++) {
            int cc = bn + wn * 32 + nt * 8 + nq;
            float2 v0 = make_float2(acc[mt][nt][0], acc[mt][nt][1]);
            float2 v1 = make_float2(acc[mt][nt][2], acc[mt][nt][3]);
            if (EPI == 1) {
                v0.x = 1.f / (1.f + expf(-v0.x));
                v0.y = 1.f / (1.f + expf(-v0.y));
                v1.x = 1.f / (1.f + expf(-v1.x));
                v1.y = 1.f / (1.f + expf(-v1.y));
            }
            if (EPI == 0) {
                float* C = (float*)Cout;
                *reinterpret_cast<float2*>(C + (size_t)r0 * Ntotal + cc) = v0;
                *reinterpret_cast<float2*>(C + (size_t)(r0 + 8) * Ntotal + cc) = v1;
            } else {
                __half* C = (__half*)Cout;
                *reinterpret_cast<__half2*>(C + (size_t)r0 * Ntotal + cc) =
                    __floats2half2_rn(v0.x, v0.y);
                *reinterpret_cast<__half2*>(C + (size_t)(r0 + 8) * Ntotal + cc) =
                    __floats2half2_rn(v1.x, v1.y);
            }
        }
    }
}

// ===================== merged fp32 -> fp16 convert (4 tensors, 1 launch) =====
#define CVT_Q0 (BL * D_MODEL / 4)
#define CVT_Q1 (INNER * D_MODEL / 4)
__global__ __launch_bounds__(256)
void cvt_f16_all(const float* __restrict__ s0, __half* __restrict__ d0,
                 const float* __restrict__ s1, __half* __restrict__ d1,
                 const float* __restrict__ s2, __half* __restrict__ d2,
                 const float* __restrict__ s3, __half* __restrict__ d3)
{
    long long q = (long long)blockIdx.x * 256 + threadIdx.x;
    const float* src; __half* dst;
    if (q < CVT_Q0)                  { src = s0; dst = d0; }
    else if ((q -= CVT_Q0) < CVT_Q1) { src = s1; dst = d1; }
    else if ((q -= CVT_Q1) < CVT_Q1) { src = s2; dst = d2; }
    else if ((q -= CVT_Q1) < CVT_Q1) { src = s3; dst = d3; }
    else return;
    long long i = q * 4;
    float4 v = *reinterpret_cast<const float4*>(src + i);
    *reinterpret_cast<__half2*>(dst + i)     = __halves2half2(__float2half_rn(v.x), __float2half_rn(v.y));
    *reinterpret_cast<__half2*>(dst + i + 2) = __halves2half2(__float2half_rn(v.z), __float2half_rn(v.w));
}

// ---------------- conv(K=4) + SiLU + dt: temporal blocking -----------------
// Block = 16 timesteps x 4096 channels; 512 threads; thread owns 8 channels
// and walks 16 timesteps with register history. Reads (16+3) rows instead of
// 16x4: L1 amplification 4x -> 1.19x.
#define CLPB 16

__global__ __launch_bounds__(512)
void conv_dt_kernel(const __half* __restrict__ proj,
                    const float* __restrict__ cw,
                    const float* __restrict__ cbias,
                    const float* __restrict__ dtw,
                    const float* __restrict__ dtb,
                    __half* __restrict__ Xout,
                    float* __restrict__ dt_out)
{
    const int blk = blockIdx.x;                    // 0..BL/CLPB-1
    const int b = blk / (SEQLEN / CLPB);
    const int lb = blk % (SEQLEN / CLPB);
    const int l0 = lb * CLPB;
    const int tid = threadIdx.x;                   // 0..511
    const int c0 = tid * 8;
    const size_t base = ((size_t)b * SEQLEN + l0) * INNER + c0;

    __shared__ float spart[CLPB][NHEADS][8];       // 32KB

    // per-channel constants
    float4 cwv[8];
#pragma unroll
    for (int j = 0; j < 8; j++)
        cwv[j] = reinterpret_cast<const float4*>(cw)[c0 + j];
    float bias[8], dws[8];
    {
        float4 b0 = *reinterpret_cast<const float4*>(cbias + c0);
        float4 b1 = *reinterpret_cast<const float4*>(cbias + c0 + 4);
        bias[0]=b0.x; bias[1]=b0.y; bias[2]=b0.z; bias[3]=b0.w;
        bias[4]=b1.x; bias[5]=b1.y; bias[6]=b1.z; bias[7]=b1.w;
        float4 d0 = *reinterpret_cast<const float4*>(dtw + c0);
        float4 d1 = *reinterpret_cast<const float4*>(dtw + c0 + 4);
        dws[0]=d0.x; dws[1]=d0.y; dws[2]=d0.z; dws[3]=d0.w;
        dws[4]=d1.x; dws[5]=d1.y; dws[6]=d1.z; dws[7]=d1.w;
    }

    // register history x[k][j]: x3=oldest
    float x3[8], x2[8], x1[8];
    auto loadrow = [&](int rel, float* dst) {
        uint4 raw = *reinterpret_cast<const uint4*>(proj + base + (ptrdiff_t)rel * INNER);
        const __half2* h2 = reinterpret_cast<const __half2*>(&raw);
#pragma unroll
        for (int j = 0; j < 4; j++) {
            float2 fv = __half22float2(h2[j]);
            dst[2 * j] = fv.x; dst[2 * j + 1] = fv.y;
        }
    };
    if (l0 >= 3) {
        loadrow(-3, x3); loadrow(-2, x2); loadrow(-1, x1);
    } else {
#pragma unroll
        for (int j = 0; j < 8; j++) { x3[j] = 0.f; x2[j] = 0.f; x1[j] = 0.f; }
        if (l0 - 2 >= 0) loadrow(-2, x2);
        if (l0 - 1 >= 0) loadrow(-1, x1);
    }

    const int hh = tid >> 3;          // head (c0/64)... c0=tid*8 -> head = tid/8
    const int slot = tid & 7;

    for (int i = 0; i < CLPB; i++) {
        float x0[8];
        loadrow(i, x0);
        float dtp = 0.f;
        uint4 outv;
        __half2* oh = reinterpret_cast<__half2*>(&outv);
        float sv[8];
#pragma unroll
        for (int j = 0; j < 8; j++) {
            const float* w = reinterpret_cast<const float*>(&cwv[j]);
            float a = bias[j];
            a = fmaf(w[0], x3[j], a);
            a = fmaf(w[1], x2[j], a);
            a = fmaf(w[2], x1[j], a);
            a = fmaf(w[3], x0[j], a);
            float s = a / (1.f + expf(-a));
            sv[j] = s;
            dtp = fmaf(s, dws[j], dtp);
        }
#pragma unroll
        for (int j = 0; j < 4; j++)
            oh[j] = __floats2half2_rn(sv[2 * j], sv[2 * j + 1]);
        *reinterpret_cast<uint4*>(Xout + base + (size_t)i * INNER) = outv;
        spart[i][hh][slot] = dtp;
#pragma unroll
        for (int j = 0; j < 8; j++) { x3[j] = x2[j]; x2[j] = x1[j]; x1[j] = x0[j]; }
    }
    __syncthreads();

    // dt reduce: 16 l x 64 heads = 1024 pairs; 2 per thread
#pragma unroll
    for (int q = 0; q < 2; q++) {
        int pair = tid + q * 512;
        int i = pair >> 6;
        int h = pair & 63;
        float v = dtb[h];
#pragma unroll
        for (int k = 0; k < 8; k++) v += spart[i][h][k];
        float sp = (v > 20.f) ? v : log1pf(expf(v));
        dt_out[((size_t)(b * SEQLEN + l0 + i)) * NHEADS + h] = sp;
    }
}

// ---------------- SSM scan + output fusion (half2-vectorized) ---------------
#define NSEG 32
#define SEG (SEQLEN / NSEG)     // 128

__global__ __launch_bounds__(1024, 1)
void scan_kernel(const __half* __restrict__ X,
                 const float* __restrict__ dt,
                 const __half* __restrict__ gate,
                 const float* __restrict__ A_log,
                 const float* __restrict__ Bv,
                 const float* __restrict__ Cv,
                 const float* __restrict__ Dv,
                 __half* __restrict__ comb)
{
    const int bh = blockIdx.x;
    const int h = bh % NHEADS;
    const int b = bh / NHEADS;
    const int p2 = threadIdx.x;     // 0..31 (channel pair)
    const int s = threadIdx.y;      // 0..31 (segment)

    const int ch0 = 2 * p2;
    const int hp0 = h * HEADDIM + ch0;
    const float ac0 = -expf(A_log[hp0]);
    const float ac1 = -expf(A_log[hp0 + 1]);
    const float2 Bc = *reinterpret_cast<const float2*>(Bv + hp0);
    const float2 Cc = *reinterpret_cast<const float2*>(Cv + hp0);
    const float2 Dc = *reinterpret_cast<const float2*>(Dv + hp0);

    const size_t baseE = ((size_t)b * SEQLEN * INNER + (size_t)h * HEADDIM + ch0);
    const size_t baseDt = (size_t)b * SEQLEN * NHEADS + h;
    const int l0 = s * SEG;

    __shared__ float2 agg_a[NSEG][32];
    __shared__ float2 agg_u[NSEG][32];
    __shared__ float2 pre[NSEG][32];

    float ap0 = 1.f, ss0 = 0.f, ap1 = 1.f, ss1 = 0.f;
    for (int i = 0; i < SEG; i++) {
        int l = l0 + i;
        float d = dt[baseDt + (size_t)l * NHEADS];
        float2 xv = __half22float2(
            *reinterpret_cast<const __half2*>(X + baseE + (size_t)l * INNER));
        float a0 = expf(d * ac0), a1 = expf(d * ac1);
        ap0 *= a0; ap1 *= a1;
        ss0 = fmaf(a0, ss0, d * Bc.x * xv.x);
        ss1 = fmaf(a1, ss1, d * Bc.y * xv.y);
    }
    agg_a[s][p2] = make_float2(ap0, ap1);
    agg_u[s][p2] = make_float2(ss0, ss1);
    __syncthreads();

    if (s == 0) {
        float st0 = 0.f, st1 = 0.f;
#pragma unroll
        for (int j = 0; j < NSEG; j++) {
            pre[j][p2] = make_float2(st0, st1);
            float2 aa = agg_a[j][p2];
            float2 uu = agg_u[j][p2];
            st0 = fmaf(aa.x, st0, uu.x);
            st1 = fmaf(aa.y, st1, uu.y);
        }
    }
    __syncthreads();

    float2 sp = pre[s][p2];
    for (int i = 0; i < SEG; i++) {
        int l = l0 + i;
        size_t idx = baseE + (size_t)l * INNER;
        float d = dt[baseDt + (size_t)l * NHEADS];
        float2 xv = __half22float2(*reinterpret_cast<const __half2*>(X + idx));
        float a0 = expf(d * ac0), a1 = expf(d * ac1);
        sp.x = fmaf(a0, sp.x, d * Bc.x * xv.x);
        sp.y = fmaf(a1, sp.y, d * Bc.y * xv.y);
        float2 gv = __half22float2(*reinterpret_cast<const __half2*>(gate + idx));
        float y0 = fmaf(Cc.x, sp.x, Dc.x * xv.x) * gv.x;
        float y1 = fmaf(Cc.y, sp.y, Dc.y * xv.y) * gv.y;
        *reinterpret_cast<__half2*>(comb + idx) = __floats2half2_rn(y0, y1);
    }
}

// ===================== host side ============================================
typedef CUresult (*TmEncodeFn)(CUtensorMap*, CUtensorMapDataType, cuuint32_t,
                               void*, const cuuint64_t*, const cuuint64_t*,
                               const cuuint32_t*, const cuuint32_t*,
                               CUtensorMapInterleave, CUtensorMapSwizzle,
                               CUtensorMapL2promotion, CUtensorMapFloatOOBfill);

static void make_tm(TmEncodeFn fn, CUtensorMap* tm, const void* ptr,
                    int rows, int K, int boxRows)
{
    cuuint64_t dims[2]    = {(cuuint64_t)K, (cuuint64_t)rows};
    cuuint64_t strides[1] = {(cuuint64_t)K * 2};
    cuuint32_t box[2]     = {64u, (cuuint32_t)boxRows};
    cuuint32_t es[2]      = {1u, 1u};
    fn(tm, CU_TENSOR_MAP_DATA_TYPE_FLOAT16, 2, (void*)ptr,
       dims, strides, box, es,
       CU_TENSOR_MAP_INTERLEAVE_NONE, CU_TENSOR_MAP_SWIZZLE_128B,
       CU_TENSOR_MAP_L2_PROMOTION_L2_128B, CU_TENSOR_MAP_FLOAT_OOB_FILL_NONE);
}

extern "C" void kernel_launch(void* const* d_in, const int* in_sizes, int n_in,
                              void* d_out, int out_size)
{
    const float* hidden = (const float*)d_in[0];
    const float* in_w   = (const float*)d_in[1];
    const float* gate_w = (const float*)d_in[2];
    const float* out_w  = (const float*)d_in[3];
    const float* conv_w = (const float*)d_in[4];
    const float* conv_b = (const float*)d_in[5];
    const float* dt_w   = (const float*)d_in[6];
    const float* dt_b   = (const float*)d_in[7];
    const float* A_log  = (const float*)d_in[8];
    const float* Bv     = (const float*)d_in[9];
    const float* Cv     = (const float*)d_in[10];
    const float* Dv     = (const float*)d_in[11];
    float* out          = (float*)d_out;

    float* dtbuf;
    __half *hx, *iw, *gw, *ow, *projh, *gateh, *xh, *cbuf;
    cudaGetSymbolAddress((void**)&dtbuf, g_dt);
    cudaGetSymbolAddress((void**)&hx, g_hx);
    cudaGetSymbolAddress((void**)&iw, g_iw);
    cudaGetSymbolAddress((void**)&gw, g_gw);
    cudaGetSymbolAddress((void**)&ow, g_ow);
    cudaGetSymbolAddress((void**)&projh, g_projh);
    cudaGetSymbolAddress((void**)&gateh, g_gateh);
    cudaGetSymbolAddress((void**)&xh, g_xh);
    cudaGetSymbolAddress((void**)&cbuf, g_cb);

    TmEncodeFn enc = nullptr;
    {
        void* p = nullptr;
        cudaDriverEntryPointQueryResult qr;
        cudaGetDriverEntryPointByVersion("cuTensorMapEncodeTiled", &p, 12000,
                                         cudaEnableDefault, &qr);
        enc = (TmEncodeFn)p;
    }

    CUtensorMap tm_hx, tm_iw, tm_gw, tm_ow, tm_cb;
    make_tm(enc, &tm_hx, hx, BL,      D_MODEL, 128);
    make_tm(enc, &tm_iw, iw, INNER,   D_MODEL, 128);
    make_tm(enc, &tm_gw, gw, INNER,   D_MODEL, 128);
    make_tm(enc, &tm_ow, ow, D_MODEL, INNER,   128);
    make_tm(enc, &tm_cb, cbuf, BL,    INNER,   128);

    cudaFuncSetAttribute((const void*)hmma_gemm<0>,
                         cudaFuncAttributeMaxDynamicSharedMemorySize, GEMM_SMEM);
    cudaFuncSetAttribute((const void*)hmma_gemm<1>,
                         cudaFuncAttributeMaxDynamicSharedMemorySize, GEMM_SMEM);
    cudaFuncSetAttribute((const void*)hmma_gemm<2>,
                         cudaFuncAttributeMaxDynamicSharedMemorySize, GEMM_SMEM);

    // 0) all fp32->fp16 converts in one launch
    {
        long long totq = (long long)CVT_Q0 + 3LL * CVT_Q1;
        int blocks = (int)((totq + 255) / 256);
        cvt_f16_all<<<blocks, 256>>>(hidden, hx, in_w, iw, gate_w, gw, out_w, ow);
    }

    // 1) in_proj -> fp16
    {
        dim3 grid(INNER / TILE_N, BL / TILE_M);
        hmma_gemm<2><<<grid, 256, GEMM_SMEM>>>(tm_hx, tm_iw, projh, INNER, D_MODEL);
    }
    // 2) gate -> sigmoid -> fp16
    {
        dim3 grid(INNER / TILE_N, BL / TILE_M);
        hmma_gemm<1><<<grid, 256, GEMM_SMEM>>>(tm_hx, tm_gw, gateh, INNER, D_MODEL);
    }
    // 3) conv + silu + dt (temporal blocking: 16 timesteps per block)
    conv_dt_kernel<<<BL / CLPB, 512>>>(projh, conv_w, conv_b, dt_w, dt_b, xh, dtbuf);
    // 4) SSM scan (half2-vectorized) fused with y, gate
    {
        dim3 blk(32, NSEG);
        scan_kernel<<<BATCH * NHEADS, blk>>>(xh, dtbuf, gateh, A_log, Bv, Cv, Dv, cbuf);
    }
    // 5) out_proj -> fp32 final
    {
        dim3 grid(D_MODEL / TILE_N, BL / TILE_M);
        hmma_gemm<0><<<grid, 256, GEMM_SMEM>>>(tm_cb, tm_ow, out, D_MODEL, INNER);
    }
}